// round 2
// baseline (speedup 1.0000x reference)
#include <cuda_runtime.h>
#include <cuda_fp16.h>
#include <cstdint>

// ---------------- problem constants ----------------
#define BATCH   4096
#define IN_F    512
#define OUT_F   512
#define GRID_N  8
#define KSPLINE (IN_F * GRID_N)      // 4096
#define KDIM    (KSPLINE + IN_F)     // 4608

// ---------------- scratch (static device globals: allocation-free) ----------
__device__ __half F_buf[(size_t)BATCH * KDIM];   // ~36 MB fp16 features
__device__ __half W_buf[(size_t)OUT_F * KDIM];   // ~4.5 MB fp16 weights

// ---------------- helpers ----------------
__device__ __forceinline__ uint32_t smem_u32(const void* p) {
    uint32_t a;
    asm("{ .reg .u64 t; cvta.to.shared.u64 t, %1; cvt.u32.u64 %0, t; }"
        : "=r"(a) : "l"(p));
    return a;
}

#define SMEM_SWZ(off) ((off) ^ (((off) >> 3) & 0x70))

__device__ __forceinline__ void ldsm4(uint32_t& r0, uint32_t& r1,
                                      uint32_t& r2, uint32_t& r3,
                                      uint32_t addr) {
    asm volatile("ldmatrix.sync.aligned.m8n8.x4.shared.b16 {%0,%1,%2,%3}, [%4];"
                 : "=r"(r0), "=r"(r1), "=r"(r2), "=r"(r3) : "r"(addr));
}

__device__ __forceinline__ void mma16816(float* c, const uint32_t* a,
                                         uint32_t b0, uint32_t b1) {
    asm volatile(
        "mma.sync.aligned.m16n8k16.row.col.f32.f16.f16.f32 "
        "{%0,%1,%2,%3}, {%4,%5,%6,%7}, {%8,%9}, {%0,%1,%2,%3};"
        : "+f"(c[0]), "+f"(c[1]), "+f"(c[2]), "+f"(c[3])
        : "r"(a[0]), "r"(a[1]), "r"(a[2]), "r"(a[3]), "r"(b0), "r"(b1));
}

// ---------------- prep kernels ----------------
__global__ void prep_w_kernel(const float* __restrict__ sw,
                              const float* __restrict__ ba) {
    int idx = blockIdx.x * blockDim.x + threadIdx.x;
    if (idx >= OUT_F * KDIM) return;
    int o = idx / KDIM;
    int k = idx - o * KDIM;
    float v;
    if (k < KSPLINE)
        v = sw[(size_t)o * KSPLINE + k];          // (o,i,g) row-major == K layout
    else
        v = 0.1f * ba[(size_t)o * IN_F + (k - KSPLINE)];
    W_buf[idx] = __float2half(v);
}

__global__ void prep_f_kernel(const float* __restrict__ x,
                              const float* __restrict__ gp) {
    int idx = blockIdx.x * blockDim.x + threadIdx.x;   // one per (b, i)
    if (idx >= BATCH * IN_F) return;
    int b = idx / IN_F;
    int i = idx - b * IN_F;
    float xn = tanhf(x[idx]);

    __half hv[8];
#pragma unroll
    for (int g = 0; g < 8; g++) {
        float d = fabsf(xn - __ldg(&gp[g]));
        float v;
        if (d < 0.5f) {
            v = 1.0f + d * d * (6.0f * d - 6.0f);      // 1 - 6d^2 + 6d^3
        } else if (d < 1.0f) {
            float t = 1.0f - d;
            v = 2.0f * t * t * t;
        } else {
            v = 0.0f;
        }
        hv[g] = __float2half(v);
    }
    *reinterpret_cast<uint4*>(&F_buf[(size_t)b * KDIM + (size_t)i * 8]) =
        *reinterpret_cast<const uint4*>(hv);
    F_buf[(size_t)b * KDIM + KSPLINE + i] = __float2half(xn);
}

// ---------------- mma.sync GEMM: D = F @ W^T ----------------
#define TM 128
#define TN 128
#define KC 64                        // fp16 per K-chunk (128B rows)
#define NITER (KDIM / KC)            // 72
#define STAGES 4
#define GEMM_THREADS 256
#define TILE_BYTES  (128 * 128)      // one 128x64 fp16 tile = 16 KB
#define STAGE_BYTES (2 * TILE_BYTES) // A + B = 32 KB
#define SMEM_DYN_TOTAL (1024 + STAGES * STAGE_BYTES)

__device__ __forceinline__ void load_stage(uint32_t tiles_base, int it,
                                           int tid, int m0, int n0) {
    uint32_t abase = tiles_base + (uint32_t)(it % STAGES) * STAGE_BYTES;
    uint32_t bbase = abase + TILE_BYTES;
    size_t k0 = (size_t)it * KC;
    const __half* Fs = F_buf + (size_t)m0 * KDIM + k0;
    const __half* Ws = W_buf + (size_t)n0 * KDIM + k0;
#pragma unroll
    for (int c = 0; c < 8; c++) {
        int chunk = tid + c * GEMM_THREADS;   // 0..2047 (16B chunks)
        int isB = chunk >> 10;
        int cc = chunk & 1023;
        int row = cc >> 3;
        int q = cc & 7;
        const __half* src = (isB ? Ws : Fs) + (size_t)row * KDIM + q * 8;
        uint32_t dst = (isB ? bbase : abase) + SMEM_SWZ((uint32_t)(row * 128 + q * 16));
        asm volatile("cp.async.cg.shared.global [%0], [%1], 16;"
                     :: "r"(dst), "l"(src));
    }
    asm volatile("cp.async.commit_group;" ::: "memory");
}

__global__ void __launch_bounds__(GEMM_THREADS, 1)
kan_gemm_kernel(float* __restrict__ out) {
    extern __shared__ char smem[];
    uint32_t tiles_base = (smem_u32(smem) + 1023u) & ~1023u;

    int tid = threadIdx.x;
    int wid = tid >> 5;
    int lane = tid & 31;
    int m0 = (blockIdx.x >> 2) * TM;     // 32 M-tiles
    int n0 = (blockIdx.x & 3) * TN;      // 4 N-tiles

    // warp sub-tile: 2 (M) x 4 (N) warps, each 64x32
    int wm = (wid >> 2) * 64;
    int wn = (wid & 3) * 32;

    // ldmatrix lane mappings
    int a_row = lane & 15;                            // row within 16-row frag
    int a_kh  = (lane >> 4) << 3;                     // +0/+8 halves (k)
    int b_nr  = (lane & 7) + ((lane >> 4) << 3);      // row within 16-col block
    int b_kh  = ((lane >> 3) & 1) << 3;               // +0/+8 halves (k)

    float acc[4][4][4];
#pragma unroll
    for (int i = 0; i < 4; i++)
#pragma unroll
        for (int j = 0; j < 4; j++)
#pragma unroll
            for (int t = 0; t < 4; t++) acc[i][j][t] = 0.0f;

    // preload STAGES-1 stages
#pragma unroll
    for (int s = 0; s < STAGES - 1; s++) load_stage(tiles_base, s, tid, m0, n0);

    for (int it = 0; it < NITER; it++) {
        // wait for stage `it` (in-order group completion)
        if (it <= NITER - 3) {
            asm volatile("cp.async.wait_group %0;" :: "n"(STAGES - 2) : "memory");
        } else if (it == NITER - 2) {
            asm volatile("cp.async.wait_group 1;" ::: "memory");
        } else {
            asm volatile("cp.async.wait_group 0;" ::: "memory");
        }
        __syncthreads();

        if (it + STAGES - 1 < NITER)
            load_stage(tiles_base, it + STAGES - 1, tid, m0, n0);

        uint32_t Ab = tiles_base + (uint32_t)(it % STAGES) * STAGE_BYTES;
        uint32_t Bb = Ab + TILE_BYTES;

#pragma unroll
        for (int ks = 0; ks < 4; ks++) {
            uint32_t a[4][4];
#pragma unroll
            for (int mi = 0; mi < 4; mi++) {
                uint32_t addr = Ab + SMEM_SWZ(
                    (uint32_t)((wm + mi * 16 + a_row) * 128 + (ks * 16 + a_kh) * 2));
                ldsm4(a[mi][0], a[mi][1], a[mi][2], a[mi][3], addr);
            }
            uint32_t b[8];
#pragma unroll
            for (int j = 0; j < 2; j++) {
                uint32_t addr = Bb + SMEM_SWZ(
                    (uint32_t)((wn + j * 16 + b_nr) * 128 + (ks * 16 + b_kh) * 2));
                ldsm4(b[j * 4 + 0], b[j * 4 + 1], b[j * 4 + 2], b[j * 4 + 3], addr);
            }
#pragma unroll
            for (int mi = 0; mi < 4; mi++)
#pragma unroll
                for (int nb = 0; nb < 4; nb++)
                    mma16816(acc[mi][nb], a[mi], b[nb * 2], b[nb * 2 + 1]);
        }
    }

    // epilogue: register accumulators -> gmem (float2 stores)
    int g = lane >> 2;
    int q = lane & 3;
#pragma unroll
    for (int mi = 0; mi < 4; mi++) {
#pragma unroll
        for (int nb = 0; nb < 4; nb++) {
            int row = m0 + wm + mi * 16 + g;
            int col = n0 + wn + nb * 8 + q * 2;
            float2 v0 = make_float2(acc[mi][nb][0], acc[mi][nb][1]);
            float2 v1 = make_float2(acc[mi][nb][2], acc[mi][nb][3]);
            *reinterpret_cast<float2*>(&out[(size_t)row * OUT_F + col]) = v0;
            *reinterpret_cast<float2*>(&out[(size_t)(row + 8) * OUT_F + col]) = v1;
        }
    }
}

// ---------------- launch ----------------
extern "C" void kernel_launch(void* const* d_in, const int* in_sizes, int n_in,
                              void* d_out, int out_size) {
    const float* x  = (const float*)d_in[0];   // (4096, 512)
    const float* sw = (const float*)d_in[1];   // (512, 512, 8)
    const float* ba = (const float*)d_in[2];   // (512, 512)
    const float* gp = (const float*)d_in[3];   // (8,)
    float* out = (float*)d_out;                // (4096, 512)

    prep_w_kernel<<<(OUT_F * KDIM + 255) / 256, 256>>>(sw, ba);
    prep_f_kernel<<<(BATCH * IN_F + 255) / 256, 256>>>(x, gp);

    cudaFuncSetAttribute(kan_gemm_kernel,
                         cudaFuncAttributeMaxDynamicSharedMemorySize,
                         SMEM_DYN_TOTAL);
    kan_gemm_kernel<<<(BATCH / TM) * (OUT_F / TN), GEMM_THREADS,
                      SMEM_DYN_TOTAL>>>(out);
}

// round 3
// speedup vs baseline: 1.1683x; 1.1683x over previous
#include <cuda_runtime.h>
#include <cuda_fp16.h>
#include <cstdint>

// ---------------- problem constants ----------------
#define BATCH   4096
#define IN_F    512
#define OUT_F   512
#define GRID_N  8
#define KSPLINE (IN_F * GRID_N)      // 4096
#define KDIM    (KSPLINE + IN_F)     // 4608

// ---------------- scratch (static device globals: allocation-free) ----------
__device__ __half F_buf[(size_t)BATCH * KDIM];   // ~36 MB fp16 features
__device__ __half W_buf[(size_t)OUT_F * KDIM];   // ~4.5 MB fp16 weights

// ---------------- helpers ----------------
__device__ __forceinline__ uint32_t smem_u32(const void* p) {
    uint32_t a;
    asm("{ .reg .u64 t; cvta.to.shared.u64 t, %1; cvt.u32.u64 %0, t; }"
        : "=r"(a) : "l"(p));
    return a;
}

#define SMEM_SWZ(off) ((off) ^ (((off) >> 3) & 0x70))

__device__ __forceinline__ void ldsm4(uint32_t& r0, uint32_t& r1,
                                      uint32_t& r2, uint32_t& r3,
                                      uint32_t addr) {
    asm volatile("ldmatrix.sync.aligned.m8n8.x4.shared.b16 {%0,%1,%2,%3}, [%4];"
                 : "=r"(r0), "=r"(r1), "=r"(r2), "=r"(r3) : "r"(addr));
}

__device__ __forceinline__ void mma16816(float* c, const uint32_t* a,
                                         uint32_t b0, uint32_t b1) {
    asm volatile(
        "mma.sync.aligned.m16n8k16.row.col.f32.f16.f16.f32 "
        "{%0,%1,%2,%3}, {%4,%5,%6,%7}, {%8,%9}, {%0,%1,%2,%3};"
        : "+f"(c[0]), "+f"(c[1]), "+f"(c[2]), "+f"(c[3])
        : "r"(a[0]), "r"(a[1]), "r"(a[2]), "r"(a[3]), "r"(b0), "r"(b1));
}

// ---------------- merged prep kernel ----------------
// Blocks [0, W_BLOCKS): cast spline_weight + 0.1*base into W_buf (8 elems/thread)
// Blocks [W_BLOCKS, W_BLOCKS+F_BLOCKS): tanh + bspline basis into F_buf
#define W_BLOCKS ((OUT_F * KDIM / 8) / 256)          // 1152
#define F_BLOCKS ((BATCH * IN_F) / 256)              // 8192

__global__ void prep_kernel(const float* __restrict__ x,
                            const float* __restrict__ sw,
                            const float* __restrict__ ba,
                            const float* __restrict__ gp) {
    if (blockIdx.x < W_BLOCKS) {
        // ---- W prep: one thread handles 8 contiguous k ----
        int idx8 = blockIdx.x * 256 + threadIdx.x;     // 0 .. 294911
        int o   = idx8 / (KDIM / 8);                   // /576
        int kq  = idx8 - o * (KDIM / 8);
        int k   = kq * 8;
        float v[8];
        if (k < KSPLINE) {
            const float4* src = reinterpret_cast<const float4*>(
                sw + (size_t)o * KSPLINE + k);
            float4 f0 = src[0], f1 = src[1];
            v[0]=f0.x; v[1]=f0.y; v[2]=f0.z; v[3]=f0.w;
            v[4]=f1.x; v[5]=f1.y; v[6]=f1.z; v[7]=f1.w;
        } else {
            const float4* src = reinterpret_cast<const float4*>(
                ba + (size_t)o * IN_F + (k - KSPLINE));
            float4 f0 = src[0], f1 = src[1];
            v[0]=0.1f*f0.x; v[1]=0.1f*f0.y; v[2]=0.1f*f0.z; v[3]=0.1f*f0.w;
            v[4]=0.1f*f1.x; v[5]=0.1f*f1.y; v[6]=0.1f*f1.z; v[7]=0.1f*f1.w;
        }
        __half hv[8];
#pragma unroll
        for (int t = 0; t < 8; t++) hv[t] = __float2half(v[t]);
        *reinterpret_cast<uint4*>(&W_buf[(size_t)o * KDIM + k]) =
            *reinterpret_cast<const uint4*>(hv);
    } else {
        // ---- F prep: one thread per (b, i) ----
        int idx = (blockIdx.x - W_BLOCKS) * 256 + threadIdx.x;
        int b = idx >> 9;            // /512
        int i = idx & 511;
        float xn = tanhf(x[idx]);

        __half hv[8];
#pragma unroll
        for (int g = 0; g < 8; g++) {
            float d = fabsf(xn - __ldg(&gp[g]));
            float vv;
            if (d < 0.5f) {
                vv = 1.0f + d * d * (6.0f * d - 6.0f);   // 1 - 6d^2 + 6d^3
            } else if (d < 1.0f) {
                float t = 1.0f - d;
                vv = 2.0f * t * t * t;
            } else {
                vv = 0.0f;
            }
            hv[g] = __float2half(vv);
        }
        *reinterpret_cast<uint4*>(&F_buf[(size_t)b * KDIM + (size_t)i * 8]) =
            *reinterpret_cast<const uint4*>(hv);
        F_buf[(size_t)b * KDIM + KSPLINE + i] = __float2half(xn);
    }
}

// ---------------- mma.sync GEMM: D = F @ W^T ----------------
#define TM 128
#define TN 128
#define KC 128                        // fp16 per K-chunk (two 128B half-blocks)
#define NITER (KDIM / KC)             // 36
#define STAGES 3
#define GEMM_THREADS 256
#define HALF_TILE_BYTES (128 * 128)   // 128 rows x 64 k fp16 = 16 KB
#define TILE_BYTES  (2 * HALF_TILE_BYTES)      // 128x128 fp16 = 32 KB
#define STAGE_BYTES (2 * TILE_BYTES)           // A + B = 64 KB
#define SMEM_DYN_TOTAL (1024 + STAGES * STAGE_BYTES)

__device__ __forceinline__ void load_stage(uint32_t tiles_base, int it,
                                           int tid, int m0, int n0) {
    uint32_t abase = tiles_base + (uint32_t)(it % STAGES) * STAGE_BYTES;
    size_t k0 = (size_t)it * KC;
    const __half* Fs = F_buf + (size_t)m0 * KDIM + k0;
    const __half* Ws = W_buf + (size_t)n0 * KDIM + k0;
    // 4096 16B-chunks per stage: [A kb0 | A kb1 | B kb0 | B kb1], 1024 each
#pragma unroll
    for (int c = 0; c < 16; c++) {
        int chunk = tid + c * GEMM_THREADS;     // 0..4095
        int isB  = chunk >> 11;
        int sub  = chunk & 2047;
        int kb   = sub >> 10;                   // k-half (0: k<64, 1: k>=64)
        int row  = (sub >> 3) & 127;
        int q    = sub & 7;
        const __half* src = (isB ? Ws : Fs) + (size_t)row * KDIM + kb * 64 + q * 8;
        uint32_t dst = abase + (uint32_t)isB * TILE_BYTES
                     + (uint32_t)kb * HALF_TILE_BYTES
                     + SMEM_SWZ((uint32_t)(row * 128 + q * 16));
        asm volatile("cp.async.cg.shared.global [%0], [%1], 16;"
                     :: "r"(dst), "l"(src));
    }
    asm volatile("cp.async.commit_group;" ::: "memory");
}

__global__ void __launch_bounds__(GEMM_THREADS, 1)
kan_gemm_kernel(float* __restrict__ out) {
    extern __shared__ char smem[];
    uint32_t tiles_base = (smem_u32(smem) + 1023u) & ~1023u;

    int tid = threadIdx.x;
    int wid = tid >> 5;
    int lane = tid & 31;
    int m0 = (blockIdx.x >> 2) * TM;     // 32 M-tiles
    int n0 = (blockIdx.x & 3) * TN;      // 4 N-tiles

    // warp sub-tile: 2 (M) x 4 (N) warps, each 64x32
    int wm = (wid >> 2) * 64;
    int wn = (wid & 3) * 32;

    // ldmatrix lane mappings
    int a_row = lane & 15;                            // row within 16-row frag
    int a_kh  = (lane >> 4) << 3;                     // +0/+8 halves (k)
    int b_nr  = (lane & 7) + ((lane >> 4) << 3);      // row within 16-col block
    int b_kh  = ((lane >> 3) & 1) << 3;               // +0/+8 halves (k)

    float acc[4][4][4];
#pragma unroll
    for (int i = 0; i < 4; i++)
#pragma unroll
        for (int j = 0; j < 4; j++)
#pragma unroll
            for (int t = 0; t < 4; t++) acc[i][j][t] = 0.0f;

    // preload STAGES-1 stages
#pragma unroll
    for (int s = 0; s < STAGES - 1; s++) load_stage(tiles_base, s, tid, m0, n0);

    for (int it = 0; it < NITER; it++) {
        if (it < NITER - 1) {
            asm volatile("cp.async.wait_group 1;" ::: "memory");
        } else {
            asm volatile("cp.async.wait_group 0;" ::: "memory");
        }
        __syncthreads();

        if (it + STAGES - 1 < NITER)
            load_stage(tiles_base, it + STAGES - 1, tid, m0, n0);

        uint32_t Ab = tiles_base + (uint32_t)(it % STAGES) * STAGE_BYTES;
        uint32_t Bb = Ab + TILE_BYTES;

#pragma unroll
        for (int ks = 0; ks < 8; ks++) {
            uint32_t kboff = (uint32_t)(ks >> 2) * HALF_TILE_BYTES;
            int kk = (ks & 3) * 16;
            uint32_t a[4][4];
#pragma unroll
            for (int mi = 0; mi < 4; mi++) {
                uint32_t addr = Ab + kboff + SMEM_SWZ(
                    (uint32_t)((wm + mi * 16 + a_row) * 128 + (kk + a_kh) * 2));
                ldsm4(a[mi][0], a[mi][1], a[mi][2], a[mi][3], addr);
            }
            uint32_t b[8];
#pragma unroll
            for (int j = 0; j < 2; j++) {
                uint32_t addr = Bb + kboff + SMEM_SWZ(
                    (uint32_t)((wn + j * 16 + b_nr) * 128 + (kk + b_kh) * 2));
                ldsm4(b[j * 4 + 0], b[j * 4 + 1], b[j * 4 + 2], b[j * 4 + 3], addr);
            }
#pragma unroll
            for (int mi = 0; mi < 4; mi++)
#pragma unroll
                for (int nb = 0; nb < 4; nb++)
                    mma16816(acc[mi][nb], a[mi], b[nb * 2], b[nb * 2 + 1]);
        }
    }

    // epilogue: register accumulators -> gmem (float2 stores)
    int g = lane >> 2;
    int q = lane & 3;
#pragma unroll
    for (int mi = 0; mi < 4; mi++) {
#pragma unroll
        for (int nb = 0; nb < 4; nb++) {
            int row = m0 + wm + mi * 16 + g;
            int col = n0 + wn + nb * 8 + q * 2;
            float2 v0 = make_float2(acc[mi][nb][0], acc[mi][nb][1]);
            float2 v1 = make_float2(acc[mi][nb][2], acc[mi][nb][3]);
            *reinterpret_cast<float2*>(&out[(size_t)row * OUT_F + col]) = v0;
            *reinterpret_cast<float2*>(&out[(size_t)(row + 8) * OUT_F + col]) = v1;
        }
    }
}

// ---------------- launch ----------------
extern "C" void kernel_launch(void* const* d_in, const int* in_sizes, int n_in,
                              void* d_out, int out_size) {
    const float* x  = (const float*)d_in[0];   // (4096, 512)
    const float* sw = (const float*)d_in[1];   // (512, 512, 8)
    const float* ba = (const float*)d_in[2];   // (512, 512)
    const float* gp = (const float*)d_in[3];   // (8,)
    float* out = (float*)d_out;                // (4096, 512)

    prep_kernel<<<W_BLOCKS + F_BLOCKS, 256>>>(x, sw, ba, gp);

    cudaFuncSetAttribute(kan_gemm_kernel,
                         cudaFuncAttributeMaxDynamicSharedMemorySize,
                         SMEM_DYN_TOTAL);
    kan_gemm_kernel<<<(BATCH / TM) * (OUT_F / TN), GEMM_THREADS,
                      SMEM_DYN_TOTAL>>>(out);
}